// round 10
// baseline (speedup 1.0000x reference)
#include <cuda_runtime.h>
#include <cuda_fp16.h>

// LDPC BP, (7,4) Hamming, 5 iters, B=262144.
// R10: R9 f16x2 compute core (2 elements/thread in half2 lanes), but
// barrier-free direct I/O: 14 contiguous floats/thread = 7 aligned float2
// LDG.64 + 7 STG.64. No smem, no __syncthreads -> warps fully independent,
// DRAM latency hidden by cross-warp overlap instead of fenced per block.
// Half-domain: Th=(llr+total)/2, mh=m_new/2, t=tanh(Th-mh), out=4*Th_final.
// rows r0={0,2,4,6}, r1={1,2,5,6}, r2={3,4,5,6}; deg={1,1,2,1,2,2,3}.

#define TPB 256

__device__ __forceinline__ __half2 h2tanh_fast(__half2 x) {
    __half2 y;
    asm("tanh.approx.f16x2 %0, %1;"
        : "=r"(reinterpret_cast<unsigned&>(y))
        : "r"(reinterpret_cast<unsigned&>(x)));
    return y;
}

__global__ __launch_bounds__(TPB)
void ldpc_bp_kernel(const float2* __restrict__ llr2, float2* __restrict__ out2) {
    int i = blockIdx.x * TPB + threadIdx.x;

    // thread i: elements 2i (lane lo) and 2i+1 (lane hi); 14 floats = 7 float2
    const float2* p = llr2 + (size_t)i * 7;
    float2 f0 = p[0], f1 = p[1], f2 = p[2], f3 = p[3], f4 = p[4], f5 = p[5], f6 = p[6];

    // a = floats[0..6], b = floats[7..13]; pack (a_v, b_v) per variable
    __half2 l0 = __floats2half2_rn(f0.x, f3.y);
    __half2 l1 = __floats2half2_rn(f0.y, f4.x);
    __half2 l2 = __floats2half2_rn(f1.x, f4.y);
    __half2 l3 = __floats2half2_rn(f1.y, f5.x);
    __half2 l4 = __floats2half2_rn(f2.x, f5.y);
    __half2 l5 = __floats2half2_rn(f2.y, f6.x);
    __half2 l6 = __floats2half2_rn(f3.x, f6.y);

    const __half2 H05 = __float2half2_rn(0.5f);
    const __half2 H1  = __float2half2_rn(1.0f);

    // deg-1: B = l+1 (kept for output), c = 0.5*tanh(B), const for iters>=2
    __half2 B0 = __hadd2(l0, H1), B1 = __hadd2(l1, H1), B3 = __hadd2(l3, H1);
    __half2 c0h = __hmul2(H05, h2tanh_fast(B0));
    __half2 c1h = __hmul2(H05, h2tanh_fast(B1));
    __half2 c3h = __hmul2(H05, h2tanh_fast(B3));

    __half2 base2 = __hadd2(l2, H05);
    __half2 base4 = __hadd2(l4, H05);
    __half2 base5 = __hadd2(l5, H05);
    __half2 base6 = l6;

    __half2 T2, T4, T5, T6;
    __half2 m01, m02, m03, m11, m12, m13, m21, m22, m23;

    // ---------- iteration 1: args = l/2, shared per variable ----------
    {
        __half2 tv0 = h2tanh_fast(__hmul2(H05, l0));
        __half2 tv1 = h2tanh_fast(__hmul2(H05, l1));
        __half2 tv2 = h2tanh_fast(__hmul2(H05, l2));
        __half2 tv3 = h2tanh_fast(__hmul2(H05, l3));
        __half2 tv4 = h2tanh_fast(__hmul2(H05, l4));
        __half2 tv5 = h2tanh_fast(__hmul2(H05, l5));
        __half2 tv6 = h2tanh_fast(__hmul2(H05, l6));

        __half2 t0h = __hmul2(H05, tv0), t1h = __hmul2(H05, tv1), t3h = __hmul2(H05, tv3);
        __half2 pb0 = __hmul2(tv4, tv6), pa0 = __hmul2(t0h, tv2);
        m01 = __hmul2(t0h, pb0);  m02 = __hmul2(pa0, tv6);  m03 = __hmul2(pa0, tv4);
        __half2 pb1 = __hmul2(tv5, tv6), pa1 = __hmul2(t1h, tv2);
        m11 = __hmul2(t1h, pb1);  m12 = __hmul2(pa1, tv6);  m13 = __hmul2(pa1, tv5);
        __half2 pa2 = __hmul2(t3h, tv4);
        m21 = __hmul2(t3h, pb1);  // pb2 == tv5*tv6 == pb1
        m22 = __hmul2(pa2, tv6);  m23 = __hmul2(pa2, tv5);

        T2 = __hadd2(base2, __hadd2(m01, m11));
        T4 = __hadd2(base4, __hadd2(m02, m21));
        T5 = __hadd2(base5, __hadd2(m12, m22));
        T6 = __hadd2(base6, __hadd2(__hadd2(m03, m13), m23));
    }

    // ---------- iterations 2..4 ----------
#pragma unroll
    for (int it = 0; it < 3; ++it) {
        __half2 t01 = h2tanh_fast(__hsub2(T2, m01));
        __half2 t02 = h2tanh_fast(__hsub2(T4, m02));
        __half2 t03 = h2tanh_fast(__hsub2(T6, m03));
        __half2 t11 = h2tanh_fast(__hsub2(T2, m11));
        __half2 t12 = h2tanh_fast(__hsub2(T5, m12));
        __half2 t13 = h2tanh_fast(__hsub2(T6, m13));
        __half2 t21 = h2tanh_fast(__hsub2(T4, m21));
        __half2 t22 = h2tanh_fast(__hsub2(T5, m22));
        __half2 t23 = h2tanh_fast(__hsub2(T6, m23));

        __half2 pb0 = __hmul2(t02, t03), pa0 = __hmul2(c0h, t01);
        m01 = __hmul2(c0h, pb0);  m02 = __hmul2(pa0, t03);  m03 = __hmul2(pa0, t02);
        __half2 pb1 = __hmul2(t12, t13), pa1 = __hmul2(c1h, t11);
        m11 = __hmul2(c1h, pb1);  m12 = __hmul2(pa1, t13);  m13 = __hmul2(pa1, t12);
        __half2 pb2 = __hmul2(t22, t23), pa2 = __hmul2(c3h, t21);
        m21 = __hmul2(c3h, pb2);  m22 = __hmul2(pa2, t23);  m23 = __hmul2(pa2, t22);

        T2 = __hadd2(base2, __hadd2(m01, m11));
        T4 = __hadd2(base4, __hadd2(m02, m21));
        T5 = __hadd2(base5, __hadd2(m12, m22));
        T6 = __hadd2(base6, __hadd2(__hadd2(m03, m13), m23));
    }

    // ---------- iteration 5 (also deg-1 messages) ----------
    __half2 m00, m10, m20;
    {
        __half2 t01 = h2tanh_fast(__hsub2(T2, m01));
        __half2 t02 = h2tanh_fast(__hsub2(T4, m02));
        __half2 t03 = h2tanh_fast(__hsub2(T6, m03));
        __half2 t11 = h2tanh_fast(__hsub2(T2, m11));
        __half2 t12 = h2tanh_fast(__hsub2(T5, m12));
        __half2 t13 = h2tanh_fast(__hsub2(T6, m13));
        __half2 t21 = h2tanh_fast(__hsub2(T4, m21));
        __half2 t22 = h2tanh_fast(__hsub2(T5, m22));
        __half2 t23 = h2tanh_fast(__hsub2(T6, m23));

        __half2 pb0 = __hmul2(t02, t03), pa0 = __hmul2(c0h, t01);
        m01 = __hmul2(c0h, pb0);  m02 = __hmul2(pa0, t03);  m03 = __hmul2(pa0, t02);
        m00 = __hmul2(t01, __hmul2(H05, pb0));
        __half2 pb1 = __hmul2(t12, t13), pa1 = __hmul2(c1h, t11);
        m11 = __hmul2(c1h, pb1);  m12 = __hmul2(pa1, t13);  m13 = __hmul2(pa1, t12);
        m10 = __hmul2(t11, __hmul2(H05, pb1));
        __half2 pb2 = __hmul2(t22, t23), pa2 = __hmul2(c3h, t21);
        m21 = __hmul2(c3h, pb2);  m22 = __hmul2(pa2, t23);  m23 = __hmul2(pa2, t22);
        m20 = __hmul2(t21, __hmul2(H05, pb2));

        T2 = __hadd2(base2, __hadd2(m01, m11));
        T4 = __hadd2(base4, __hadd2(m02, m21));
        T5 = __hadd2(base5, __hadd2(m12, m22));
        T6 = __hadd2(base6, __hadd2(__hadd2(m03, m13), m23));
    }

    // outputs: 4 * Th_final (x4 in half is exact exponent shift)
    const __half2 H4 = __float2half2_rn(4.0f);
    __half2 O0 = __hmul2(H4, __hadd2(B0, m00));
    __half2 O1 = __hmul2(H4, __hadd2(B1, m10));
    __half2 O2 = __hmul2(H4, T2);
    __half2 O3 = __hmul2(H4, __hadd2(B3, m20));
    __half2 O4 = __hmul2(H4, T4);
    __half2 O5 = __hmul2(H4, T5);
    __half2 O6 = __hmul2(H4, T6);

    float2* q = out2 + (size_t)i * 7;
    // element a (low lanes) -> floats [0..6], element b (high lanes) -> [7..13]
    q[0] = make_float2(__low2float(O0),  __low2float(O1));
    q[1] = make_float2(__low2float(O2),  __low2float(O3));
    q[2] = make_float2(__low2float(O4),  __low2float(O5));
    q[3] = make_float2(__low2float(O6),  __high2float(O0));
    q[4] = make_float2(__high2float(O1), __high2float(O2));
    q[5] = make_float2(__high2float(O3), __high2float(O4));
    q[6] = make_float2(__high2float(O5), __high2float(O6));
}

extern "C" void kernel_launch(void* const* d_in, const int* in_sizes, int n_in,
                              void* d_out, int out_size) {
    const float2* llr2 = (const float2*)d_in[0];
    float2* out2 = (float2*)d_out;
    int B = in_sizes[0] / 7;            // 262144
    int blocks = B / (TPB * 2);         // 512 blocks, 2 elements/thread
    ldpc_bp_kernel<<<blocks, TPB>>>(llr2, out2);
}

// round 11
// speedup vs baseline: 1.2316x; 1.2316x over previous
#include <cuda_runtime.h>
#include <cuda_fp16.h>

// LDPC BP, (7,4) Hamming, 5 iters, B=262144.
// R11: ONE element/thread (8192 warps = best occupancy shape) with EDGES
// packed in half2 lanes. Rows 0,1 are isomorphic -> lane-packed with no
// cross-lane ops; row 2 handled with 3 swaps/iter. 27 MUFU slots total.
//
// Half-domain: Th=(llr+total)/2, mh=m_new/2, t=tanh(Th-mh), out=4*Th_final.
// rows r0={0,2,4,6}, r1={1,2,5,6}, r2={3,4,5,6}; deg={1,1,2,1,2,2,3}
// Lane layout: lane0 = row0 quantity, lane1 = row1 quantity.
//   M1=(m01,m11) msgs to v2; M2=(m02,m12) msgs to v4/v5; M3=(m03,m13) msgs to v6
//   M2r=(m21,m22) row2 msgs to v4/v5; m23b = broadcast row2 msg to v6
//   T2b=(T2,T2); T45=(T4,T5); T6b=(T6,T6)

#define TPB 256

__device__ __forceinline__ __half2 h2tanh_fast(__half2 x) {
    __half2 y;
    asm("tanh.approx.f16x2 %0, %1;"
        : "=r"(reinterpret_cast<unsigned&>(y))
        : "r"(reinterpret_cast<unsigned&>(x)));
    return y;
}
__device__ __forceinline__ __half2 hswap(__half2 x) { return __lowhigh2highlow(x); }

__global__ __launch_bounds__(TPB)
void ldpc_bp_kernel(const float* __restrict__ llr, float* __restrict__ out, int B) {
    int b = blockIdx.x * TPB + threadIdx.x;
    if (b >= B) return;

    const float* p = llr + (size_t)b * 7;
    float l0 = p[0], l1 = p[1], l2 = p[2], l3 = p[3], l4 = p[4], l5 = p[5], l6 = p[6];

    const __half2 H05 = __float2half2_rn(0.5f);

    // constants (iters >= 2): deg-1 edge t is fixed at tanh(l+1)
    __half2 B01 = __floats2half2_rn(l0 + 1.f, l1 + 1.f);   // kept for outputs too
    __half2 B3b = __float2half2_rn(l3 + 1.f);
    __half2 C01 = __hmul2(H05, h2tanh_fast(B01));          // (c0h, c1h)
    __half2 c3b = __hmul2(H05, h2tanh_fast(B3b));          // broadcast c3h

    __half2 B2b = __float2half2_rn(l2 + 0.5f);
    __half2 B45 = __floats2half2_rn(l4 + 0.5f, l5 + 0.5f);
    __half2 B6b = __float2half2_rn(l6);

    __half2 M1, M2, M3, M2r, m23b, T2b, T45, T6b;

    // ---------- iteration 1: all edge args = l_v/2 ----------
    {
        __half2 t2  = h2tanh_fast(__float2half2_rn(0.5f * l2));                 // bcast
        __half2 t3  = h2tanh_fast(__floats2half2_rn(0.5f * l4, 0.5f * l5));
        __half2 t4  = h2tanh_fast(__float2half2_rn(0.5f * l6));                 // bcast
        __half2 ca  = __hmul2(H05, h2tanh_fast(__floats2half2_rn(0.5f * l0, 0.5f * l1)));
        __half2 c3i = __hmul2(H05, h2tanh_fast(__float2half2_rn(0.5f * l3)));   // bcast

        __half2 pb = __hmul2(t3, t4);
        __half2 pa = __hmul2(ca, t2);
        M1 = __hmul2(ca, pb);
        M2 = __hmul2(pa, t4);
        M3 = __hmul2(pa, t3);

        __half2 sty = hswap(t3);           // row2 edge pair (v4,v5) == t3 at iter1
        __half2 u   = __hmul2(t3, sty);    // bcast t21*t22
        __half2 w   = __hmul2(c3i, t4);    // bcast c3*t23
        M2r  = __hmul2(w, sty);            // (m21, m22)
        m23b = __hmul2(c3i, u);            // bcast m23

        T2b = __hadd2(B2b, __hadd2(M1, hswap(M1)));
        T6b = __hadd2(B6b, __hadd2(__hadd2(M3, hswap(M3)), m23b));
        T45 = __hadd2(B45, __hadd2(M2, M2r));
    }

    // ---------- iterations 2..4 ----------
#pragma unroll
    for (int it = 0; it < 3; ++it) {
        __half2 t2  = h2tanh_fast(__hsub2(T2b, M1));
        __half2 t3  = h2tanh_fast(__hsub2(T45, M2));
        __half2 t4  = h2tanh_fast(__hsub2(T6b, M3));
        __half2 ty1 = h2tanh_fast(__hsub2(T45, M2r));   // (t21, t22)
        __half2 ty2 = h2tanh_fast(__hsub2(T6b, m23b));  // bcast t23

        __half2 pb = __hmul2(t3, t4);
        __half2 pa = __hmul2(C01, t2);
        M1 = __hmul2(C01, pb);
        M2 = __hmul2(pa, t4);
        M3 = __hmul2(pa, t3);

        __half2 sty = hswap(ty1);
        __half2 u   = __hmul2(ty1, sty);
        __half2 w   = __hmul2(c3b, ty2);
        M2r  = __hmul2(w, sty);
        m23b = __hmul2(c3b, u);

        T2b = __hadd2(B2b, __hadd2(M1, hswap(M1)));
        T6b = __hadd2(B6b, __hadd2(__hadd2(M3, hswap(M3)), m23b));
        T45 = __hadd2(B45, __hadd2(M2, M2r));
    }

    // ---------- iteration 5 (also deg-1 messages for outputs) ----------
    __half2 Mdeg, m20b;
    {
        __half2 t2  = h2tanh_fast(__hsub2(T2b, M1));
        __half2 t3  = h2tanh_fast(__hsub2(T45, M2));
        __half2 t4  = h2tanh_fast(__hsub2(T6b, M3));
        __half2 ty1 = h2tanh_fast(__hsub2(T45, M2r));
        __half2 ty2 = h2tanh_fast(__hsub2(T6b, m23b));

        __half2 pb = __hmul2(t3, t4);
        __half2 pa = __hmul2(C01, t2);
        M1 = __hmul2(C01, pb);
        M2 = __hmul2(pa, t4);
        M3 = __hmul2(pa, t3);
        Mdeg = __hmul2(H05, __hmul2(t2, pb));   // (m00, m10)

        __half2 sty = hswap(ty1);
        __half2 u   = __hmul2(ty1, sty);
        __half2 w   = __hmul2(c3b, ty2);
        M2r  = __hmul2(w, sty);
        m23b = __hmul2(c3b, u);
        m20b = __hmul2(H05, __hmul2(u, ty2));   // bcast m20 = 0.5*t21*t22*t23

        T2b = __hadd2(B2b, __hadd2(M1, hswap(M1)));
        T6b = __hadd2(B6b, __hadd2(__hadd2(M3, hswap(M3)), m23b));
        T45 = __hadd2(B45, __hadd2(M2, M2r));
    }

    // outputs: out = 4 * Th_final
    __half2 O01 = __hadd2(B01, Mdeg);      // (Th0, Th1)
    __half2 O3  = __hadd2(B3b, m20b);      // bcast Th3

    float* q = out + (size_t)b * 7;
    q[0] = 4.0f * __low2float(O01);
    q[1] = 4.0f * __high2float(O01);
    q[2] = 4.0f * __low2float(T2b);
    q[3] = 4.0f * __low2float(O3);
    q[4] = 4.0f * __low2float(T45);
    q[5] = 4.0f * __high2float(T45);
    q[6] = 4.0f * __low2float(T6b);
}

extern "C" void kernel_launch(void* const* d_in, const int* in_sizes, int n_in,
                              void* d_out, int out_size) {
    const float* llr = (const float*)d_in[0];
    float* out = (float*)d_out;
    int B = in_sizes[0] / 7;  // 262144

    const int threads = TPB;
    int blocks = (B + threads - 1) / threads;  // 1024
    ldpc_bp_kernel<<<blocks, threads>>>(llr, out, B);
}